// round 3
// baseline (speedup 1.0000x reference)
#include <cuda_runtime.h>
#include <math.h>

#define BB 16
#define SS 2048
#define DD 512
#define NGROUPS 8
#define GC 64          // channels per group
#define KW 5
#define STILE 256      // seq positions per conv block

// Scratch (device globals -- no allocation allowed)
__device__ float g_actT[BB * DD * SS];   // activated, transposed [b][c][s]; later reused for ln out
__device__ float g_noise[BB * SS * DD];  // noise [b][s][d]
__device__ float g_inv;                  // 1 / max(||freq_filter||, 1e-12)

// packed fp32x2 helpers
#define FMA_F32X2(d, a, b, c) \
    asm("fma.rn.f32x2 %0, %1, %2, %3;" : "=l"(d) : "l"(a), "l"(b), "l"(c))
#define PACK2(d, lo, hi) \
    asm("mov.b64 %0, {%1, %2};" : "=l"(d) : "r"(lo), "r"(hi))
#define UNPACK2(lo, hi, s) \
    asm("mov.b64 {%0, %1}, %2;" : "=r"(lo), "=r"(hi) : "l"(s))

__device__ __forceinline__ float2 cmulf(float2 a, float2 b) {
    return make_float2(fmaf(a.x, b.x, -a.y * b.y), fmaf(a.x, b.y, a.y * b.x));
}
__device__ __forceinline__ float2 caddf(float2 a, float2 b) {
    return make_float2(a.x + b.x, a.y + b.y);
}
__device__ __forceinline__ float2 csubf(float2 a, float2 b) {
    return make_float2(a.x - b.x, a.y - b.y);
}

// ---------------------------------------------------------------- kernel 0
__global__ void k0_norm(const float* __restrict__ ff) {
    __shared__ float red[256];
    int tid = threadIdx.x;
    float v = 0.f;
    for (int i = tid; i < DD; i += 256) { float f = ff[i]; v += f * f; }
    red[tid] = v;
    __syncthreads();
    for (int s = 128; s > 0; s >>= 1) {
        if (tid < s) red[tid] += red[tid + s];
        __syncthreads();
    }
    if (tid == 0) g_inv = 1.0f / fmaxf(sqrtf(red[0]), 1e-12f);
}

// ---------------------------------------------------------------- kernel 1
// filtered = clip(x * fnorm, +-10); grouped conv over seq (K=5, pad 2);
// activated = tanh(conv + b) + 0.1*filtered; write transposed [b][c][s].
// 512 threads, 256-seq tile, fp32x2 packed FMAs over output-channel pairs.
__global__ void __launch_bounds__(512) k1_conv(
    const float* __restrict__ x, const float* __restrict__ ff,
    const float* __restrict__ w, const float* __restrict__ cb)
{
    extern __shared__ float sm[];
    float* ysm = sm;                   // [64 ch][264] (260 used: 256 + halo 2+2)
    float* wsm = sm + GC * 264;        // [i][k][o] : 64*5*64

    const int g  = blockIdx.y;
    const int b  = blockIdx.z;
    const int s0 = blockIdx.x * STILE;
    const int tid = threadIdx.x;
    const float inv = g_inv;

    // weights: gmem w[((g*64+o)*64+i)*5+k] -> smem wsm[(i*5+k)*64+o]
    for (int idx = tid; idx < GC * GC * KW; idx += 512) {
        int o = idx / (GC * KW);
        int r = idx - o * (GC * KW);
        int i = r / KW;
        int k = r - i * KW;
        wsm[(i * KW + k) * GC + o] = w[((g * GC + o) * GC + i) * KW + k];
    }
    // input tile: filtered, clipped, zero padded (260 cols)
    for (int idx = tid; idx < 260 * GC; idx += 512) {
        int i  = idx & 63;
        int j  = idx >> 6;
        int sg = s0 + j - 2;
        float v = 0.f;
        if (sg >= 0 && sg < SS) {
            int c = g * GC + i;
            v = x[(b * SS + sg) * DD + c] * (ff[c] * inv);
            v = fminf(fmaxf(v, -10.f), 10.f);
        }
        ysm[i * 264 + j] = v;
    }
    __syncthreads();

    const int so = tid & 63;   // 4-s slab -> covers 256 s
    const int oo = tid >> 6;   // 8-o slab (0..7)

    unsigned long long acc2[4][4];
#pragma unroll
    for (int a = 0; a < 4; ++a)
#pragma unroll
        for (int c = 0; c < 4; ++c) acc2[a][c] = 0ull;

#pragma unroll 2
    for (int i = 0; i < GC; ++i) {
        const float* yr = &ysm[i * 264 + so * 4];
        float4 y0 = *(const float4*)(yr);
        float4 y1 = *(const float4*)(yr + 4);
        float ya[8] = {y0.x, y0.y, y0.z, y0.w, y1.x, y1.y, y1.z, y1.w};
        unsigned long long y2[8];
#pragma unroll
        for (int j = 0; j < 8; ++j) {
            unsigned int u = __float_as_uint(ya[j]);
            PACK2(y2[j], u, u);
        }
#pragma unroll
        for (int k = 0; k < KW; ++k) {
            const float* wr = &wsm[(i * KW + k) * GC + oo * 8];
            ulonglong2 wa = *(const ulonglong2*)(wr);
            ulonglong2 wb = *(const ulonglong2*)(wr + 4);
            unsigned long long w2[4] = {wa.x, wa.y, wb.x, wb.y};
#pragma unroll
            for (int ts = 0; ts < 4; ++ts)
#pragma unroll
                for (int op = 0; op < 4; ++op)
                    FMA_F32X2(acc2[ts][op], y2[ts + k], w2[op], acc2[ts][op]);
        }
    }

#pragma unroll
    for (int op = 0; op < 4; ++op) {
#pragma unroll
        for (int h = 0; h < 2; ++h) {
            int ol = oo * 8 + op * 2 + h;
            float bias = cb[g * GC + ol];
            float4 o4;
            float* po = (float*)&o4;
#pragma unroll
            for (int ts = 0; ts < 4; ++ts) {
                unsigned int lo, hi;
                UNPACK2(lo, hi, acc2[ts][op]);
                float av = __uint_as_float(h ? hi : lo);
                float filt = ysm[ol * 264 + so * 4 + ts + 2];
                po[ts] = tanhf(av + bias) + 0.1f * filt;
            }
            *(float4*)&g_actT[((b * DD) + g * GC + ol) * SS + s0 + so * 4] = o4;
        }
    }
}

// ---------------------------------------------------------------- kernel 2
// Per block: 8 channels = 4 complex seqs of length 2048.
// z = colA + i*colB ; z' = ifft(fft(z) .* s_sym) ; re/im are the two
// filtered columns (s_sym real & conjugate-symmetric).
// Radix-2 DIF forward / DIT inverse, with pairs of stages fused into
// radix-4 passes (same permutation => scaling stays in bit-reversed domain).
__global__ void __launch_bounds__(512) k2_fft()
{
    extern __shared__ float2 Zs[];          // 4*2048 data + 1024 twiddles
    float2* tws = Zs + 4 * 2048;
    const int tid = threadIdx.x;
    const int b  = blockIdx.y;
    const int d0 = blockIdx.x * 8;

    for (int j = tid; j < 1024; j += 512) {
        float sv, cv;
        sincosf(-3.14159265358979323846f * (float)j * (1.0f / 1024.0f), &sv, &cv);
        tws[j] = make_float2(cv, sv);
    }
    for (int idx = tid; idx < 4 * 512; idx += 512) {
        int q = idx >> 9, n4 = idx & 511;
        const float4 ra = *(const float4*)&g_actT[((b * DD) + d0 + 2 * q) * SS + n4 * 4];
        const float4 rb = *(const float4*)&g_actT[((b * DD) + d0 + 2 * q + 1) * SS + n4 * 4];
        float2* zp = Zs + q * 2048 + n4 * 4;
        zp[0] = make_float2(ra.x, rb.x);
        zp[1] = make_float2(ra.y, rb.y);
        zp[2] = make_float2(ra.z, rb.z);
        zp[3] = make_float2(ra.w, rb.w);
    }
    __syncthreads();

    // ---- forward: 5 radix-4 (paired radix-2 DIF) passes, spans (1024,512)...(4,2)
    {
        const int ls_arr[5] = {9, 7, 5, 3, 1};   // log2(s), s = 512,128,32,8,2
#pragma unroll 1
        for (int p = 0; p < 5; ++p) {
            const int ls = ls_arr[p];
            const int s = 1 << ls;
            const int stepA = 512 >> ls;         // stage A: span 2s
#pragma unroll 1
            for (int it = 0; it < 4; ++it) {
                int bt = tid + it * 512;
                int q = bt >> 9, t = bt & 511;
                int j = t & (s - 1);
                int m = t >> ls;
                int a = (m << (ls + 2)) + j;
                float2* Zq = Zs + q * 2048;
                float2 t0 = Zq[a], t1 = Zq[a + s], t2 = Zq[a + 2 * s], t3 = Zq[a + 3 * s];
                float2 w1 = tws[j * stepA];
                float2 w2 = tws[2 * j * stepA];
                float2 A0 = caddf(t0, t2);
                float2 A2 = cmulf(csubf(t0, t2), w1);
                float2 A1 = caddf(t1, t3);
                float2 tmp = cmulf(csubf(t1, t3), w1);
                float2 A3 = make_float2(tmp.y, -tmp.x);       // * (-i)
                Zq[a]         = caddf(A0, A1);
                Zq[a + s]     = cmulf(csubf(A0, A1), w2);
                Zq[a + 2 * s] = caddf(A2, A3);
                Zq[a + 3 * s] = cmulf(csubf(A2, A3), w2);
            }
            __syncthreads();
        }
    }

    // ---- fused: final forward stage (span=1, tw=1) + spectral scaling (bit-rev domain, +1/N)
#pragma unroll 1
    for (int it = 0; it < 8; ++it) {
        int bt = tid + it * 512;
        int q = bt >> 10, p = bt & 1023;
        float2* Zq = Zs + q * 2048;
        float4 zz = *(float4*)&Zq[2 * p];
        float2 u = make_float2(zz.x, zz.y), v = make_float2(zz.z, zz.w);
        float2 r0 = caddf(u, v), r1 = csubf(u, v);
        int k0 = __brev((unsigned)(2 * p)) >> 21;
        int k1 = k0 | 1024;
        int kk0 = min(k0, 2048 - k0);
        int kk1 = 2048 - k1;
        float b0 = fminf(fmaxf(sqrtf((float)kk0 * (1.0f / 2048.0f) + 1e-8f), 1e-8f), 1e6f);
        float b1 = fminf(fmaxf(sqrtf((float)kk1 * (1.0f / 2048.0f) + 1e-8f), 1e-8f), 1e6f);
        float sc0 = (1.0f / b0) * (1.0f / 2048.0f);
        float sc1 = (1.0f / b1) * (1.0f / 2048.0f);
        float4 oz = make_float4(r0.x * sc0, r0.y * sc0, r1.x * sc1, r1.y * sc1);
        *(float4*)&Zq[2 * p] = oz;
    }
    __syncthreads();

    // ---- inverse: 5 radix-4 (paired radix-2 DIT) passes, spans (1,2)...(256,512)
    {
        const int ls_arr[5] = {0, 2, 4, 6, 8};   // s = 1,4,16,64,256
#pragma unroll 1
        for (int p = 0; p < 5; ++p) {
            const int ls = ls_arr[p];
            const int s = 1 << ls;
            const int stepA = 512 >> ls;         // stage A': span 2s
            const int stepB = 1024 >> ls;        // stage B': span s
#pragma unroll 1
            for (int it = 0; it < 4; ++it) {
                int bt = tid + it * 512;
                int q = bt >> 9, t = bt & 511;
                int j = t & (s - 1);
                int m = t >> ls;
                int a = (m << (ls + 2)) + j;
                float2* Zq = Zs + q * 2048;
                float2 t0 = Zq[a], t1 = Zq[a + s], t2 = Zq[a + 2 * s], t3 = Zq[a + 3 * s];
                float2 tw2 = tws[j * stepB];
                float2 cw2 = make_float2(tw2.x, -tw2.y);
                float2 tw1 = tws[j * stepA];
                float2 cw1 = make_float2(tw1.x, -tw1.y);
                float2 v1 = cmulf(t1, cw2), v3 = cmulf(t3, cw2);
                float2 B0 = caddf(t0, v1), B1 = csubf(t0, v1);
                float2 B2 = caddf(t2, v3), B3 = csubf(t2, v3);
                float2 C  = cmulf(B2, cw1);
                float2 E  = cmulf(B3, cw1);
                float2 Ei = make_float2(-E.y, E.x);           // * (+i)
                Zq[a]         = caddf(B0, C);
                Zq[a + 2 * s] = csubf(B0, C);
                Zq[a + s]     = caddf(B1, Ei);
                Zq[a + 3 * s] = csubf(B1, Ei);
            }
            __syncthreads();
        }
    }

    // ---- fused: final inverse stage (span=1024) + clip + store to [b][s][d]
#pragma unroll 1
    for (int it = 0; it < 2; ++it) {
        int n = tid + it * 512;                  // n in [0,1024)
        float2 tw = tws[n];
        float2 cw = make_float2(tw.x, -tw.y);
        float lo[8], hi[8];
#pragma unroll
        for (int q = 0; q < 4; ++q) {
            float2 u = Zs[q * 2048 + n];
            float2 v = Zs[q * 2048 + n + 1024];
            float2 vw = cmulf(v, cw);
            float2 e0 = caddf(u, vw), e1 = csubf(u, vw);
            lo[2 * q]     = fminf(fmaxf(e0.x, -10.f), 10.f);
            lo[2 * q + 1] = fminf(fmaxf(e0.y, -10.f), 10.f);
            hi[2 * q]     = fminf(fmaxf(e1.x, -10.f), 10.f);
            hi[2 * q + 1] = fminf(fmaxf(e1.y, -10.f), 10.f);
        }
        float* dA = &g_noise[(b * SS + n) * DD + d0];
        float* dB = &g_noise[(b * SS + n + 1024) * DD + d0];
        *(float4*)dA       = make_float4(lo[0], lo[1], lo[2], lo[3]);
        *(float4*)(dA + 4) = make_float4(lo[4], lo[5], lo[6], lo[7]);
        *(float4*)dB       = make_float4(hi[0], hi[1], hi[2], hi[3]);
        *(float4*)(dB + 4) = make_float4(hi[4], hi[5], hi[6], hi[7]);
    }
}

// ---------------------------------------------------------------- kernel 3
// LayerNorm over last dim; warp per (b,s) row; float4 IO; result into g_actT.
__global__ void __launch_bounds__(512) k3_ln(const float* __restrict__ gamma,
                                             const float* __restrict__ beta)
{
    int warp = threadIdx.x >> 5, lane = threadIdx.x & 31;
    int row = blockIdx.x * 16 + warp;              // [0, B*S)
    const float* src = g_noise + row * DD;
    float4 v4[4];
    float sum = 0.f;
#pragma unroll
    for (int j = 0; j < 4; ++j) {
        v4[j] = *(const float4*)&src[(lane + j * 32) * 4];
        sum += v4[j].x + v4[j].y + v4[j].z + v4[j].w;
    }
#pragma unroll
    for (int o = 16; o; o >>= 1) sum += __shfl_xor_sync(0xffffffffu, sum, o);
    float mu = sum * (1.0f / 512.0f);
    float sq = 0.f;
#pragma unroll
    for (int j = 0; j < 4; ++j) {
        float a0 = v4[j].x - mu, a1 = v4[j].y - mu, a2 = v4[j].z - mu, a3 = v4[j].w - mu;
        sq += a0 * a0 + a1 * a1 + a2 * a2 + a3 * a3;
    }
#pragma unroll
    for (int o = 16; o; o >>= 1) sq += __shfl_xor_sync(0xffffffffu, sq, o);
    float rstd = rsqrtf(sq * (1.0f / 512.0f) + 1e-5f);
    float* dst = g_actT + row * DD;                // reuse buffer
#pragma unroll
    for (int j = 0; j < 4; ++j) {
        int d = (lane + j * 32) * 4;
        float4 gm = *(const float4*)&gamma[d];
        float4 bt = *(const float4*)&beta[d];
        float4 o4;
        o4.x = (v4[j].x - mu) * rstd * gm.x + bt.x;
        o4.y = (v4[j].y - mu) * rstd * gm.y + bt.y;
        o4.z = (v4[j].z - mu) * rstd * gm.z + bt.z;
        o4.w = (v4[j].w - mu) * rstd * gm.w + bt.w;
        *(float4*)&dst[d] = o4;
    }
}

// ---------------------------------------------------------------- kernel 4
// EMA: m[0]=ln[0]; m[t]=a*ln[t]+(1-a)*m[t-1]. (15/16)^256 ~ 7e-8, so
// chunks of 256 outputs with a 256-step lookback are independent.
// 128 threads per block (d quarter) for better wave balance.
__global__ void __launch_bounds__(128) k4_ema(float* __restrict__ out)
{
    const int d  = blockIdx.z * 128 + threadIdx.x;
    const int b  = blockIdx.y;
    const int t0 = blockIdx.x * 256;
    const float* src = g_actT + (b * SS) * DD + d;
    float* dst = out + (b * SS) * DD + d;
    const float a = 0.0625f, na = 0.9375f;
    float m;
    int t;
    if (t0 == 0) {
        m = src[0];
        dst[0] = m;
        t = 1;
    } else {
        m = 0.f;
        t = t0 - 256;
    }
    const int tend = t0 + 256;
    for (; t < t0; ++t) m = fmaf(na, m, a * src[t * DD]);      // lookback
    for (; t < tend; ++t) {
        m = fmaf(na, m, a * src[t * DD]);
        dst[t * DD] = m;
    }
}

// ---------------------------------------------------------------- launch
extern "C" void kernel_launch(void* const* d_in, const int* in_sizes, int n_in,
                              void* d_out, int out_size)
{
    const float* x     = (const float*)d_in[0];
    const float* ff    = (const float*)d_in[1];
    const float* cw    = (const float*)d_in[2];
    const float* cb    = (const float*)d_in[3];
    const float* gamma = (const float*)d_in[4];
    const float* beta  = (const float*)d_in[5];
    float* out = (float*)d_out;

    const int k1_smem = (GC * 264 + GC * KW * GC) * (int)sizeof(float);
    const int k2_smem = (4 * 2048 + 1024) * (int)sizeof(float2);
    cudaFuncSetAttribute(k1_conv, cudaFuncAttributeMaxDynamicSharedMemorySize, k1_smem);
    cudaFuncSetAttribute(k2_fft,  cudaFuncAttributeMaxDynamicSharedMemorySize, k2_smem);

    k0_norm<<<1, 256>>>(ff);
    k1_conv<<<dim3(SS / STILE, NGROUPS, BB), 512, k1_smem>>>(x, ff, cw, cb);
    k2_fft<<<dim3(DD / 8, BB), 512, k2_smem>>>();
    k3_ln<<<(BB * SS) / 16, 512>>>(gamma, beta);
    k4_ema<<<dim3(SS / 256, BB, 4), 128>>>(out);
}

// round 4
// speedup vs baseline: 1.2063x; 1.2063x over previous
#include <cuda_runtime.h>
#include <math.h>

#define BB 16
#define SS 2048
#define DD 512
#define NGROUPS 8
#define GC 64
#define KW 5
#define STILE 256

__device__ float g_actT[BB * DD * SS];   // [b][c][s]; later reused for ln out
__device__ float g_noise[BB * SS * DD];  // [b][s][d]
__device__ float g_inv;

#define FMA_F32X2(d, a, b, c) \
    asm("fma.rn.f32x2 %0, %1, %2, %3;" : "=l"(d) : "l"(a), "l"(b), "l"(c))
#define PACK2(d, lo, hi) \
    asm("mov.b64 %0, {%1, %2};" : "=l"(d) : "r"(lo), "r"(hi))
#define UNPACK2(lo, hi, s) \
    asm("mov.b64 {%0, %1}, %2;" : "=r"(lo), "=r"(hi) : "l"(s))

union PKU { float2 f; unsigned long long u; };
__device__ __forceinline__ float2 caddp(float2 a, float2 b) {
    PKU x, y, r; x.f = a; y.f = b;
    asm("add.rn.f32x2 %0, %1, %2;" : "=l"(r.u) : "l"(x.u), "l"(y.u));
    return r.f;
}
__device__ __forceinline__ float2 csubp(float2 a, float2 b) {
    PKU x, y, r; x.f = a; y.f = b;
    asm("fma.rn.f32x2 %0, %1, %2, %3;"
        : "=l"(r.u) : "l"(y.u), "l"(0xBF800000BF800000ULL), "l"(x.u));
    return r.f;
}
__device__ __forceinline__ float2 cmulc(float2 a, float2 b) {   // a*b
    return make_float2(fmaf(a.x, b.x, -a.y * b.y), fmaf(a.x, b.y, a.y * b.x));
}
__device__ __forceinline__ float2 cmuljc(float2 v, float2 t) {  // v*conj(t)
    return make_float2(fmaf(v.x, t.x, v.y * t.y), fmaf(v.y, t.x, -v.x * t.y));
}
__device__ __forceinline__ float2 C8v(int r) {  // exp(-i*pi*r/8)
    const float c = 0.92387953251128676f, s = 0.38268343236508977f,
                h = 0.70710678118654752f;
    switch (r & 7) {
        case 0: return make_float2(1.f, 0.f);
        case 1: return make_float2(c, -s);
        case 2: return make_float2(h, -h);
        case 3: return make_float2(s, -c);
        case 4: return make_float2(0.f, -1.f);
        case 5: return make_float2(-s, -c);
        case 6: return make_float2(-h, -h);
        default: return make_float2(-c, -s);
    }
}

// DIF fwd: (u,v)->(u+v,(u-v)*T).  DIT inv: w=v*conj(T); (u,v)->(u+w,u-w)
#define BF(U, V, T)  { float2 _s = caddp(U, V), _d = csubp(U, V); U = _s; V = cmulc(_d, T); }
#define BF1(U, V)    { float2 _s = caddp(U, V), _d = csubp(U, V); U = _s; V = _d; }
#define BI(U, V, T)  { float2 _w = cmuljc(V, T); float2 _u = caddp(U, _w); V = csubp(U, _w); U = _u; }
#define BI1(U, V)    { float2 _w = V; float2 _u = caddp(U, _w); V = csubp(U, _w); U = _u; }

// 4 fwd radix-2 stages on register bits (spans 8b,4b,2b,b of base), base twiddle w1
__device__ __forceinline__ void fwd_group4(float2* X, float2 w1) {
    float2 w2 = cmulc(w1, w1), w4 = cmulc(w2, w2), w8 = cmulc(w4, w4);
#pragma unroll
    for (int r = 0; r < 8; ++r) { float2 T = cmulc(w1, C8v(r)); BF(X[r], X[r + 8], T); }
#pragma unroll
    for (int h = 0; h < 16; h += 8)
#pragma unroll
        for (int r = 0; r < 4; ++r) { float2 T = cmulc(w2, C8v(2 * r)); BF(X[h + r], X[h + r + 4], T); }
#pragma unroll
    for (int h = 0; h < 16; h += 4)
#pragma unroll
        for (int r = 0; r < 2; ++r) { float2 T = cmulc(w4, C8v(4 * r)); BF(X[h + r], X[h + r + 2], T); }
#pragma unroll
    for (int h = 0; h < 16; h += 2) BF(X[h], X[h + 1], w8);
}
__device__ __forceinline__ void inv_group4(float2* X, float2 w1) {
    float2 w2 = cmulc(w1, w1), w4 = cmulc(w2, w2), w8 = cmulc(w4, w4);
#pragma unroll
    for (int h = 0; h < 16; h += 2) BI(X[h], X[h + 1], w8);
#pragma unroll
    for (int h = 0; h < 16; h += 4)
#pragma unroll
        for (int r = 0; r < 2; ++r) { float2 T = cmulc(w4, C8v(4 * r)); BI(X[h + r], X[h + r + 2], T); }
#pragma unroll
    for (int h = 0; h < 16; h += 8)
#pragma unroll
        for (int r = 0; r < 4; ++r) { float2 T = cmulc(w2, C8v(2 * r)); BI(X[h + r], X[h + r + 4], T); }
#pragma unroll
    for (int r = 0; r < 8; ++r) { float2 T = cmulc(w1, C8v(r)); BI(X[r], X[r + 8], T); }
}
// fwd spans 4,2,1 within each 8-block (twiddles are pure C8)
__device__ __forceinline__ void fwd_group3(float2* X) {
#pragma unroll
    for (int h = 0; h < 16; h += 8) {
#pragma unroll
        for (int r = 0; r < 4; ++r) { float2 T = C8v(2 * r); BF(X[h + r], X[h + r + 4], T); }
#pragma unroll
        for (int u = 0; u < 8; u += 4)
#pragma unroll
            for (int r = 0; r < 2; ++r) { float2 T = C8v(4 * r); BF(X[h + u + r], X[h + u + r + 2], T); }
#pragma unroll
        for (int u = 0; u < 8; u += 2) BF1(X[h + u], X[h + u + 1]);
    }
}
__device__ __forceinline__ void inv_group3(float2* X) {
#pragma unroll
    for (int h = 0; h < 16; h += 8) {
#pragma unroll
        for (int u = 0; u < 8; u += 2) BI1(X[h + u], X[h + u + 1]);
#pragma unroll
        for (int u = 0; u < 8; u += 4)
#pragma unroll
            for (int r = 0; r < 2; ++r) { float2 T = C8v(4 * r); BI(X[h + u + r], X[h + u + r + 2], T); }
#pragma unroll
        for (int r = 0; r < 4; ++r) { float2 T = C8v(2 * r); BI(X[h + r], X[h + r + 4], T); }
    }
}

#define SF(a) ((a) + ((a) >> 4))

// ---------------------------------------------------------------- kernel 0
__global__ void k0_norm(const float* __restrict__ ff) {
    __shared__ float red[256];
    int tid = threadIdx.x;
    float v = 0.f;
    for (int i = tid; i < DD; i += 256) { float f = ff[i]; v += f * f; }
    red[tid] = v;
    __syncthreads();
    for (int s = 128; s > 0; s >>= 1) {
        if (tid < s) red[tid] += red[tid + s];
        __syncthreads();
    }
    if (tid == 0) g_inv = 1.0f / fmaxf(sqrtf(red[0]), 1e-12f);
}

// ---------------------------------------------------------------- kernel 1
__global__ void __launch_bounds__(512) k1_conv(
    const float* __restrict__ x, const float* __restrict__ ff,
    const float* __restrict__ w, const float* __restrict__ cb)
{
    extern __shared__ float sm[];
    float* ysm = sm;                   // [64][264]
    float* wsm = sm + GC * 264;        // [i][k][o]

    const int g  = blockIdx.y;
    const int b  = blockIdx.z;
    const int s0 = blockIdx.x * STILE;
    const int tid = threadIdx.x;
    const float inv = g_inv;

    for (int idx = tid; idx < GC * GC * KW; idx += 512) {
        int o = idx / (GC * KW);
        int r = idx - o * (GC * KW);
        int i = r / KW;
        int k = r - i * KW;
        wsm[(i * KW + k) * GC + o] = w[((g * GC + o) * GC + i) * KW + k];
    }
    for (int idx = tid; idx < 260 * GC; idx += 512) {
        int i  = idx & 63;
        int j  = idx >> 6;
        int sg = s0 + j - 2;
        float v = 0.f;
        if (sg >= 0 && sg < SS) {
            int c = g * GC + i;
            v = x[(b * SS + sg) * DD + c] * (ff[c] * inv);
            v = fminf(fmaxf(v, -10.f), 10.f);
        }
        ysm[i * 264 + j] = v;
    }
    __syncthreads();

    const int so = tid & 63;
    const int oo = tid >> 6;

    unsigned long long acc2[4][4];
#pragma unroll
    for (int a = 0; a < 4; ++a)
#pragma unroll
        for (int c = 0; c < 4; ++c) acc2[a][c] = 0ull;

#pragma unroll 2
    for (int i = 0; i < GC; ++i) {
        const float* yr = &ysm[i * 264 + so * 4];
        float4 y0 = *(const float4*)(yr);
        float4 y1 = *(const float4*)(yr + 4);
        float ya[8] = {y0.x, y0.y, y0.z, y0.w, y1.x, y1.y, y1.z, y1.w};
        unsigned long long y2[8];
#pragma unroll
        for (int j = 0; j < 8; ++j) {
            unsigned int u = __float_as_uint(ya[j]);
            PACK2(y2[j], u, u);
        }
#pragma unroll
        for (int k = 0; k < KW; ++k) {
            const float* wr = &wsm[(i * KW + k) * GC + oo * 8];
            ulonglong2 wa = *(const ulonglong2*)(wr);
            ulonglong2 wb = *(const ulonglong2*)(wr + 4);
            unsigned long long w2[4] = {wa.x, wa.y, wb.x, wb.y};
#pragma unroll
            for (int ts = 0; ts < 4; ++ts)
#pragma unroll
                for (int op = 0; op < 4; ++op)
                    FMA_F32X2(acc2[ts][op], y2[ts + k], w2[op], acc2[ts][op]);
        }
    }

#pragma unroll
    for (int op = 0; op < 4; ++op) {
#pragma unroll
        for (int h = 0; h < 2; ++h) {
            int ol = oo * 8 + op * 2 + h;
            float bias = cb[g * GC + ol];
            float4 o4;
            float* po = (float*)&o4;
#pragma unroll
            for (int ts = 0; ts < 4; ++ts) {
                unsigned int lo, hi;
                UNPACK2(lo, hi, acc2[ts][op]);
                float av = __uint_as_float(h ? hi : lo);
                float filt = ysm[ol * 264 + so * 4 + ts + 2];
                po[ts] = tanhf(av + bias) + 0.1f * filt;
            }
            *(float4*)&g_actT[((b * DD) + g * GC + ol) * SS + s0 + so * 4] = o4;
        }
    }
}

// ---------------------------------------------------------------- kernel 2
// Register-resident FFT: 4 complex seqs (8 channels) of 2048 per block,
// 16 points/thread. z=colA+i*colB; z'=ifft(fft(z).*s_sym); scaling applied
// in bit-reversed domain between fwd and inv stage pyramids.
__global__ void __launch_bounds__(512, 2) k2_fft()
{
    extern __shared__ float2 Zs[];      // 4 * 2176
    const int tid = threadIdx.x;
    const int q = tid >> 7;             // seq 0..3
    const int t = tid & 127;
    const int b  = blockIdx.y;
    const int d0 = blockIdx.x * 8;
    float2* Sq = Zs + q * 2176;

    // load: layout A, a = t + 128r
    float2 X[16];
    const float* pa = &g_actT[((b * DD) + d0 + 2 * q) * SS];
    const float* pb = pa + SS;
#pragma unroll
    for (int r = 0; r < 16; ++r) {
        int n = t + 128 * r;
        X[r] = make_float2(pa[n], pb[n]);
    }

    float sv, cv;
    sincosf(-3.14159265358979323846f * (float)t * (1.0f / 1024.0f), &sv, &cv);
    float2 wA = make_float2(cv, sv);

    // fwd spans 1024,512,256,128
    fwd_group4(X, wA);

    // exchange A -> B  (B: a = hi*128 + 8m + lo)
#pragma unroll
    for (int r = 0; r < 16; ++r) Sq[SF(t + 128 * r)] = X[r];
    __syncthreads();
    const int hi = t >> 3, lo = t & 7;
#pragma unroll
    for (int m = 0; m < 16; ++m) X[m] = Sq[SF(hi * 128 + 8 * m + lo)];

    sincosf(-3.14159265358979323846f * (float)lo * (1.0f / 64.0f), &sv, &cv);
    float2 wB = make_float2(cv, sv);

    // fwd spans 64,32,16,8
    fwd_group4(X, wB);

    // exchange B -> C  (C: a = hi*128 + lo*16 + e)
    __syncthreads();
#pragma unroll
    for (int m = 0; m < 16; ++m) Sq[SF(hi * 128 + 8 * m + lo)] = X[m];
    __syncthreads();
    const int abase = hi * 128 + lo * 16;
#pragma unroll
    for (int e = 0; e < 16; ++e) X[e] = Sq[SF(abase + e)];

    // fwd spans 4,2,1
    fwd_group3(X);

    // spectral scaling at bit-reversed indices (+1/N)
#pragma unroll
    for (int e = 0; e < 16; ++e) {
        int a = abase + e;
        int k = __brev((unsigned)a) >> 21;
        int kk = min(k, 2048 - k);
        float base = sqrtf((float)kk * (1.0f / 2048.0f) + 1e-8f);
        base = fminf(fmaxf(base, 1e-8f), 1e6f);
        float sc = (1.0f / base) * (1.0f / 2048.0f);
        X[e].x *= sc;
        X[e].y *= sc;
    }

    // inv spans 1,2,4 (same registers)
    inv_group3(X);

    // exchange C -> B
    __syncthreads();
#pragma unroll
    for (int e = 0; e < 16; ++e) Sq[SF(abase + e)] = X[e];
    __syncthreads();
#pragma unroll
    for (int m = 0; m < 16; ++m) X[m] = Sq[SF(hi * 128 + 8 * m + lo)];

    // inv spans 8,16,32,64
    inv_group4(X, wB);

    // exchange B -> A
    __syncthreads();
#pragma unroll
    for (int m = 0; m < 16; ++m) Sq[SF(hi * 128 + 8 * m + lo)] = X[m];
    __syncthreads();
#pragma unroll
    for (int r = 0; r < 16; ++r) X[r] = Sq[SF(t + 128 * r)];

    // inv spans 128,256,512,1024
    inv_group4(X, wA);

    // clip + stage + coalesced 32B-per-row store
    __syncthreads();
#pragma unroll
    for (int r = 0; r < 16; ++r) {
        float2 c = X[r];
        c.x = fminf(fmaxf(c.x, -10.f), 10.f);
        c.y = fminf(fmaxf(c.y, -10.f), 10.f);
        Sq[SF(t + 128 * r)] = c;
    }
    __syncthreads();
#pragma unroll 1
    for (int it = 0; it < 4; ++it) {
        int n = tid + it * 512;
        float2 z0 = Zs[0 * 2176 + SF(n)];
        float2 z1 = Zs[1 * 2176 + SF(n)];
        float2 z2 = Zs[2 * 2176 + SF(n)];
        float2 z3 = Zs[3 * 2176 + SF(n)];
        float* dst = &g_noise[(b * SS + n) * DD + d0];
        *(float4*)dst       = make_float4(z0.x, z0.y, z1.x, z1.y);
        *(float4*)(dst + 4) = make_float4(z2.x, z2.y, z3.x, z3.y);
    }
}

// ---------------------------------------------------------------- kernel 3
__global__ void __launch_bounds__(512) k3_ln(const float* __restrict__ gamma,
                                             const float* __restrict__ beta)
{
    int warp = threadIdx.x >> 5, lane = threadIdx.x & 31;
    int row = blockIdx.x * 16 + warp;
    const float* src = g_noise + row * DD;
    float4 v4[4];
    float sum = 0.f;
#pragma unroll
    for (int j = 0; j < 4; ++j) {
        v4[j] = *(const float4*)&src[(lane + j * 32) * 4];
        sum += v4[j].x + v4[j].y + v4[j].z + v4[j].w;
    }
#pragma unroll
    for (int o = 16; o; o >>= 1) sum += __shfl_xor_sync(0xffffffffu, sum, o);
    float mu = sum * (1.0f / 512.0f);
    float sq = 0.f;
#pragma unroll
    for (int j = 0; j < 4; ++j) {
        float a0 = v4[j].x - mu, a1 = v4[j].y - mu, a2 = v4[j].z - mu, a3 = v4[j].w - mu;
        sq += a0 * a0 + a1 * a1 + a2 * a2 + a3 * a3;
    }
#pragma unroll
    for (int o = 16; o; o >>= 1) sq += __shfl_xor_sync(0xffffffffu, sq, o);
    float rstd = rsqrtf(sq * (1.0f / 512.0f) + 1e-5f);
    float* dst = g_actT + row * DD;
#pragma unroll
    for (int j = 0; j < 4; ++j) {
        int d = (lane + j * 32) * 4;
        float4 gm = *(const float4*)&gamma[d];
        float4 bt = *(const float4*)&beta[d];
        float4 o4;
        o4.x = (v4[j].x - mu) * rstd * gm.x + bt.x;
        o4.y = (v4[j].y - mu) * rstd * gm.y + bt.y;
        o4.z = (v4[j].z - mu) * rstd * gm.z + bt.z;
        o4.w = (v4[j].w - mu) * rstd * gm.w + bt.w;
        *(float4*)&dst[d] = o4;
    }
}

// ---------------------------------------------------------------- kernel 4
__global__ void __launch_bounds__(128) k4_ema(float* __restrict__ out)
{
    const int d  = blockIdx.z * 128 + threadIdx.x;
    const int b  = blockIdx.y;
    const int t0 = blockIdx.x * 256;
    const float* src = g_actT + (b * SS) * DD + d;
    float* dst = out + (b * SS) * DD + d;
    const float a = 0.0625f, na = 0.9375f;
    float m;
    int t;
    if (t0 == 0) {
        m = src[0];
        dst[0] = m;
        t = 1;
    } else {
        m = 0.f;
        t = t0 - 256;
    }
    const int tend = t0 + 256;
    for (; t < t0; ++t) m = fmaf(na, m, a * src[t * DD]);
    for (; t < tend; ++t) {
        m = fmaf(na, m, a * src[t * DD]);
        dst[t * DD] = m;
    }
}

// ---------------------------------------------------------------- launch
extern "C" void kernel_launch(void* const* d_in, const int* in_sizes, int n_in,
                              void* d_out, int out_size)
{
    const float* x     = (const float*)d_in[0];
    const float* ff    = (const float*)d_in[1];
    const float* cw    = (const float*)d_in[2];
    const float* cb    = (const float*)d_in[3];
    const float* gamma = (const float*)d_in[4];
    const float* beta  = (const float*)d_in[5];
    float* out = (float*)d_out;

    const int k1_smem = (GC * 264 + GC * KW * GC) * (int)sizeof(float);
    const int k2_smem = 4 * 2176 * (int)sizeof(float2);
    cudaFuncSetAttribute(k1_conv, cudaFuncAttributeMaxDynamicSharedMemorySize, k1_smem);
    cudaFuncSetAttribute(k2_fft,  cudaFuncAttributeMaxDynamicSharedMemorySize, k2_smem);

    k0_norm<<<1, 256>>>(ff);
    k1_conv<<<dim3(SS / STILE, NGROUPS, BB), 512, k1_smem>>>(x, ff, cw, cb);
    k2_fft<<<dim3(DD / 8, BB), 512, k2_smem>>>();
    k3_ln<<<(BB * SS) / 16, 512>>>(gamma, beta);
    k4_ema<<<dim3(SS / 256, BB, 4), 128>>>(out);
}